// round 15
// baseline (speedup 1.0000x reference)
#include <cuda_runtime.h>
#include <cuda_fp16.h>
#include <math.h>
#include <stdint.h>

#define Bn 16384
#define Ln 50
#define Dn 128
#define Fn 6
#define CINn 2688
#define H1N 512
#define H2N 256

// ---------------- scratch (static device globals) ---------------------------
__device__ __align__(16) __half g_s  [Bn * Fn * Dn];   // fp16 SE-scaled feats
__device__ __align__(16) __half g_c  [Bn * CINn];      // fp16 activations
__device__ __align__(16) __half g_h1 [Bn * H1N];
__device__ __align__(16) float g_h2 [Bn * H2N];
__device__ __align__(16) __half g_w1t[H1N * CINn];     // fp16 weights (transposed)
__device__ __align__(16) __half g_w2t[H2N * H1N];
__device__ __align__(16) __half g_wb [5 * Dn * Dn];    // bi_W as [f][e][d]
__device__ __align__(16) __half g_wgt[Dn * Dn];        // gnn_W as [n=h*32+o][k=i]

// ---------------- PTX helpers (sm_80-level only) -----------------------------
__device__ __forceinline__ uint32_t smem_u32(const void* p) {
    uint32_t a;
    asm("{ .reg .u64 t; cvta.to.shared.u64 t, %1; cvt.u32.u64 %0, t; }" : "=r"(a) : "l"(p));
    return a;
}
__device__ __forceinline__ void cp16(uint32_t dst, const void* src) {
    asm volatile("cp.async.cg.shared.global [%0], [%1], 16;" :: "r"(dst), "l"(src));
}
__device__ __forceinline__ void cp_commit() {
    asm volatile("cp.async.commit_group;" ::: "memory");
}
template <int N>
__device__ __forceinline__ void cp_wait() {
    asm volatile("cp.async.wait_group %0;" :: "n"(N) : "memory");
}
__device__ __forceinline__ void ldsm4(uint32_t* r, uint32_t addr) {
    asm volatile("ldmatrix.sync.aligned.m8n8.x4.shared.b16 {%0,%1,%2,%3}, [%4];"
                 : "=r"(r[0]), "=r"(r[1]), "=r"(r[2]), "=r"(r[3]) : "r"(addr));
}
__device__ __forceinline__ void mma_fp16(float* d, const uint32_t* a, const uint32_t* b) {
    asm volatile(
        "mma.sync.aligned.m16n8k16.row.col.f32.f16.f16.f32 "
        "{%0,%1,%2,%3}, {%4,%5,%6,%7}, {%8,%9}, {%0,%1,%2,%3};"
        : "+f"(d[0]), "+f"(d[1]), "+f"(d[2]), "+f"(d[3])
        : "r"(a[0]), "r"(a[1]), "r"(a[2]), "r"(a[3]), "r"(b[0]), "r"(b[1]));
}

// ---------------- K1: fused features + GAT(HMMA) + SE ------------------------
// dynamic smem layout (bytes). W row pitch = 48 B (16-aligned for cp.async).
#define XS_OFF 0                    // xs fp32 [6*128]           3072
#define XH_OFF 3072                 // xh fp16 [16][136]         4352
#define WB_OFF 7424                 // W k-chunk, 2 stages       2*6144
#define WB_STG 6144                 //   128 rows * 48 B
#define WROW 48u
#define HP_OFF 19712                // hp fp32 [6][132]          3168
#define FG_SMEM 22880

__global__ __launch_bounds__(128) void k_feat_gnn(
    const int* __restrict__ item_id, const float* __restrict__ item_mm,
    const int* __restrict__ likes, const int* __restrict__ views,
    const int* __restrict__ item_seq, const float* __restrict__ item_emb,
    const float* __restrict__ cate_emb, const float* __restrict__ mm_w,
    const float* __restrict__ mm_b, const float* __restrict__ ln_g,
    const float* __restrict__ ln_b,
    const float* __restrict__ gnn_a,
    const float* __restrict__ se_w1, const float* __restrict__ se_b1,
    const float* __restrict__ se_w2, const float* __restrict__ se_b2)
{
    extern __shared__ char dsm[];
    float* xs = reinterpret_cast<float*>(dsm + XS_OFF);
    __half* xh = reinterpret_cast<__half*>(dsm + XH_OFF);
    float* hps = reinterpret_cast<float*>(dsm + HP_OFF);

    int b = blockIdx.x, t = threadIdx.x;
    int lane = t & 31, w = t >> 5;
    int h = w;
    __shared__ float sm[Dn];
    __shared__ float red[8];
    __shared__ float red2[4 * Fn];
    __shared__ int sseq[Ln];

    sm[t] = item_mm[b * Dn + t];
    if (t < Ln) sseq[t] = item_seq[b * Ln + t];
    __syncthreads();

    // ---- mm projection (fp32 FMA; 128 FMA/thread) ----
    float y = mm_b[t];
    {
        const float* Wc = mm_w + t;
        #pragma unroll
        for (int c = 0; c < 4; c++) {
            float wv[32];
            #pragma unroll
            for (int q = 0; q < 32; q++) wv[q] = Wc[(c * 32 + q) * Dn];
            const float4* xv = reinterpret_cast<const float4*>(&sm[c * 32]);
            #pragma unroll
            for (int q8 = 0; q8 < 8; q8++) {
                float4 v = xv[q8];
                y = fmaf(v.x, wv[q8 * 4 + 0], y);
                y = fmaf(v.y, wv[q8 * 4 + 1], y);
                y = fmaf(v.z, wv[q8 * 4 + 2], y);
                y = fmaf(v.w, wv[q8 * 4 + 3], y);
            }
        }
    }

    float s1 = y, s2 = y * y;
    #pragma unroll
    for (int o = 16; o; o >>= 1) {
        s1 += __shfl_xor_sync(0xffffffffu, s1, o);
        s2 += __shfl_xor_sync(0xffffffffu, s2, o);
    }
    if (!lane) { red[w] = s1; red[4 + w] = s2; }
    __syncthreads();
    float mu = (red[0] + red[1] + red[2] + red[3]) * (1.f / Dn);
    float m2 = (red[4] + red[5] + red[6] + red[7]) * (1.f / Dn);
    float var = m2 - mu * mu;
    float yn = (y - mu) * rsqrtf(var + 1e-5f) * ln_g[t] + ln_b[t];
    float img = 0.5f * yn * (1.f + erff(yn * 0.70710678118654752f));

    // branch-free masked mean: item_emb[0] == 0 by construction
    float hs = 0.f;
    int cnt = 0;
    #pragma unroll 10
    for (int l = 0; l < Ln; l++) {
        int id = sseq[l];
        hs += item_emb[(size_t)id * Dn + t];
        cnt += (id != 0);
    }
    float hist = hs / fmaxf((float)cnt, 1.f);

    float xv6[Fn];
    xv6[0] = 0.f;
    xv6[1] = cate_emb[likes[b] * Dn + t];
    xv6[2] = cate_emb[views[b] * Dn + t];
    xv6[3] = item_emb[(size_t)item_id[b] * Dn + t];
    xv6[4] = img;
    xv6[5] = hist;
    #pragma unroll
    for (int n = 0; n < Fn; n++) {
        xs[n * Dn + t] = xv6[n];
        xh[n * 136 + t] = __float2half(xv6[n]);
    }
    // zero pad rows 6..15 of xh
    #pragma unroll
    for (int i = 0; i < 10; i++)
        xh[(6 + i) * 136 + t] = __float2half(0.f);

    // ---- GAT projection via HMMA: hp[16,128] = xh @ Wg^T -------------------
    const uint32_t xh_u = smem_u32(xh);
    const uint32_t wb0 = smem_u32(dsm + WB_OFF);
    const uint32_t wb1 = wb0 + WB_STG;
    const uint32_t aaddr = xh_u + (uint32_t)((lane & 15) * 272 + (lane >> 4) * 16);
    const uint32_t baddr = (uint32_t)((lane & 7) + ((lane >> 4) << 3)) * WROW
                         + (uint32_t)(((lane >> 3) & 1) * 16);

    float dacc[4][4];
    #pragma unroll
    for (int j = 0; j < 4; j++)
        #pragma unroll
        for (int q = 0; q < 4; q++) dacc[j][q] = 0.f;

    // thread t streams W row t (2 cp16 per stage; dst pitch 48 B, 16-aligned)
    {
        const __half* src = g_wgt + t * Dn;
        cp16(wb0 + (uint32_t)t * WROW, src);
        cp16(wb0 + (uint32_t)t * WROW + 16, src + 8);
        cp_commit();
    }
    #pragma unroll
    for (int ks = 0; ks < 8; ks++) {
        uint32_t cur = (ks & 1) ? wb1 : wb0;
        if (ks < 7) {
            uint32_t nxt = (ks & 1) ? wb0 : wb1;
            const __half* src = g_wgt + t * Dn + (ks + 1) * 16;
            cp16(nxt + (uint32_t)t * WROW, src);
            cp16(nxt + (uint32_t)t * WROW + 16, src + 8);
            cp_commit();
            cp_wait<1>();
        } else {
            cp_wait<0>();
        }
        __syncthreads();

        uint32_t a[4];
        ldsm4(a, aaddr + ks * 32);
        uint32_t bw[2][4];
        ldsm4(bw[0], cur + (uint32_t)(h * 32) * WROW + baddr);
        ldsm4(bw[1], cur + (uint32_t)(h * 32 + 16) * WROW + baddr);
        #pragma unroll
        for (int j = 0; j < 4; j++)
            mma_fp16(dacc[j], a, &bw[j >> 1][(j & 1) * 2]);
        __syncthreads();
    }

    // D rows 0..5 -> hp smem
    {
        int row = lane >> 2;
        if (row < Fn) {
            #pragma unroll
            for (int j = 0; j < 4; j++) {
                int colb = h * 32 + j * 8 + (lane & 3) * 2;
                hps[row * 132 + colb]     = dacc[j][0];
                hps[row * 132 + colb + 1] = dacc[j][1];
            }
        }
    }
    __syncthreads();

    float hp[Fn];
    #pragma unroll
    for (int n = 0; n < Fn; n++) hp[n] = hps[n * 132 + t];

    // ---- attention + ELU + SE (unchanged) ----------------------------------
    float a1 = gnn_a[h * 64 + lane];
    float a2 = gnn_a[h * 64 + 32 + lane];
    float ei[Fn], ej[Fn];
    #pragma unroll
    for (int n = 0; n < Fn; n++) {
        float v1 = hp[n] * a1, v2 = hp[n] * a2;
        #pragma unroll
        for (int o = 16; o; o >>= 1) {
            v1 += __shfl_xor_sync(0xffffffffu, v1, o);
            v2 += __shfl_xor_sync(0xffffffffu, v2, o);
        }
        ei[n] = v1; ej[n] = v2;
    }

    float gnn[Fn];
    #pragma unroll
    for (int n = 0; n < Fn; n++) {
        float em[Fn], mx = -1e30f;
        #pragma unroll
        for (int m = 0; m < Fn; m++) {
            float e = ei[n] + ej[m];
            e = e > 0.f ? e : 0.2f * e;
            em[m] = e; mx = fmaxf(mx, e);
        }
        float ss = 0.f;
        #pragma unroll
        for (int m = 0; m < Fn; m++) { em[m] = expf(em[m] - mx); ss += em[m]; }
        float inv = 1.f / ss, acc = 0.f;
        #pragma unroll
        for (int m = 0; m < Fn; m++) acc = fmaf(em[m], hp[m], acc);
        float hn = acc * inv + xs[n * Dn + t];
        gnn[n] = hn > 0.f ? hn : expm1f(hn);
    }

    #pragma unroll
    for (int n = 0; n < Fn; n++) {
        float v = gnn[n];
        #pragma unroll
        for (int o = 16; o; o >>= 1) v += __shfl_xor_sync(0xffffffffu, v, o);
        if (!lane) red2[h * Fn + n] = v;
    }
    __syncthreads();

    float wv[Fn];
    {
        float z[Fn];
        #pragma unroll
        for (int n = 0; n < Fn; n++)
            z[n] = (red2[0 * Fn + n] + red2[1 * Fn + n] + red2[2 * Fn + n] + red2[3 * Fn + n]) * (1.f / Dn);
        float a[3];
        #pragma unroll
        for (int k = 0; k < 3; k++) {
            float v = se_b1[k];
            #pragma unroll
            for (int n = 0; n < Fn; n++) v = fmaf(z[n], se_w1[n * 3 + k], v);
            a[k] = fmaxf(v, 0.f);
        }
        #pragma unroll
        for (int f = 0; f < Fn; f++) {
            float v = se_b2[f];
            #pragma unroll
            for (int k = 0; k < 3; k++) v = fmaf(a[k], se_w2[k * 6 + f], v);
            wv[f] = 1.f / (1.f + expf(-v));
        }
    }

    __half* ch = g_c + (size_t)b * CINn;
    __half* sb = g_s + (size_t)b * Fn * Dn;
    #pragma unroll
    for (int n = 0; n < Fn; n++) {
        float v = gnn[n];
        ch[n * Dn + t] = __float2half(v);
        sb[n * Dn + t] = __float2half(v * wv[n]);
    }
}

// ---------------- weight prep ------------------------------------------------
__global__ __launch_bounds__(256) void k_wt(
    const float* __restrict__ W, __half* __restrict__ T, int K, int N)
{
    __shared__ float tile[32][33];
    int kb = blockIdx.x * 32, nb = blockIdx.y * 32;
    int tx = threadIdx.x & 31, ty = threadIdx.x >> 5;
    #pragma unroll
    for (int i = 0; i < 32; i += 8)
        tile[ty + i][tx] = W[(size_t)(kb + ty + i) * N + nb + tx];
    __syncthreads();
    #pragma unroll
    for (int i = 0; i < 32; i += 8)
        T[(size_t)(nb + ty + i) * K + kb + tx] = __float2half(tile[tx][ty + i]);
}
__global__ __launch_bounds__(256) void k_wbi(const float* __restrict__ W)
{
    __shared__ float tile[32][33];
    int f = blockIdx.z;
    int db = blockIdx.x * 32, eb = blockIdx.y * 32;
    int tx = threadIdx.x & 31, ty = threadIdx.x >> 5;
    const float* Wf = W + (size_t)f * Dn * Dn;
    __half* Tf = g_wb + (size_t)f * Dn * Dn;
    #pragma unroll
    for (int i = 0; i < 32; i += 8)
        tile[ty + i][tx] = Wf[(db + ty + i) * Dn + eb + tx];
    __syncthreads();
    #pragma unroll
    for (int i = 0; i < 32; i += 8)
        Tf[(eb + ty + i) * Dn + db + tx] = __float2half(tile[tx][ty + i]);
}
// gnn_W[h][i][o] -> g_wgt[n=h*32+o][k=i], fp16 (one-time, tiny)
__global__ __launch_bounds__(256) void k_wg(const float* __restrict__ W)
{
    int idx = blockIdx.x * 256 + threadIdx.x;
    if (idx >= 4 * 128 * 32) return;
    int h = idx >> 12, rem = idx & 4095;
    int i = rem >> 5, o = rem & 31;
    g_wgt[(h * 32 + o) * Dn + i] = __float2half(W[idx]);
}

// ---------------- shared GEMM constants --------------------------------------
#define BK 32
#define ROWB 80u

// ---------------- k_mma128: bilinear + fused pairs (coalesced epilogue) ------
#define BM 128
#define BN 128
#define OFF_A  0u
#define OFF_B  10240u
#define STAGEB 20480u
#define NSTAGE 4
#define SMEM_MMA (NSTAGE * STAGEB)
#define VP 132

__global__ __launch_bounds__(256, 1) void k_mma128(
    const __half* __restrict__ A, const __half* __restrict__ B,
    int K, int lda, long az, long bz)
{
    extern __shared__ char smem[];
    const uint32_t sbase = smem_u32(smem);
    const int tid = threadIdx.x;
    const int lane = tid & 31, wid = tid >> 5;
    const int wm = wid >> 2, wn = wid & 3;
    const int bm = blockIdx.y * BM, bn = blockIdx.x * BN;
    const int z = blockIdx.z;
    A += (size_t)z * az;
    B += (size_t)z * bz;

    float acc[4][4][4];
    #pragma unroll
    for (int mi = 0; mi < 4; mi++)
        #pragma unroll
        for (int ni = 0; ni < 4; ni++)
            #pragma unroll
            for (int q = 0; q < 4; q++) acc[mi][ni][q] = 0.f;

    const uint32_t a_base = (uint32_t)(wm * 64 + (lane & 15)) * ROWB + (uint32_t)((lane >> 4) * 16);
    const uint32_t b_base = (uint32_t)(wn * 32 + (lane & 7) + ((lane >> 4) << 3)) * ROWB
                          + (uint32_t)(((lane >> 3) & 1) * 16);

    const int nIter = K / BK;

    auto load_stage = [&](int buf, int k0) {
        uint32_t base = sbase + (uint32_t)buf * STAGEB;
        #pragma unroll
        for (int half = 0; half < 2; half++) {
            int e = tid + half * 256;
            int r = e >> 2, c = e & 3;
            uint32_t off = (uint32_t)r * ROWB + (uint32_t)c * 16;
            cp16(base + OFF_A + off, A + (size_t)(bm + r) * lda + k0 + c * 8);
            cp16(base + OFF_B + off, B + (size_t)(bn + r) * K   + k0 + c * 8);
        }
    };

    load_stage(0, 0);
    cp_commit();
    load_stage(1, BK);
    cp_commit();
    load_stage(2, 2 * BK);
    cp_commit();

    for (int it = 0; it < nIter; it++) {
        if (it + 3 < nIter) {
            load_stage((it + 3) & 3, (it + 3) * BK);
            cp_commit();
            cp_wait<3>();
        } else if (it + 2 < nIter) {
            cp_wait<2>();
        } else if (it + 1 < nIter) {
            cp_wait<1>();
        } else {
            cp_wait<0>();
        }
        __syncthreads();

        uint32_t base = sbase + (uint32_t)(it & 3) * STAGEB;
        #pragma unroll
        for (int ks = 0; ks < 2; ks++) {
            uint32_t koff = (uint32_t)ks * 32;
            uint32_t a[4][4], bb[2][4];
            #pragma unroll
            for (int mi = 0; mi < 4; mi++)
                ldsm4(a[mi], base + OFF_A + a_base + (uint32_t)mi * 16 * ROWB + koff);
            #pragma unroll
            for (int nq = 0; nq < 2; nq++)
                ldsm4(bb[nq], base + OFF_B + b_base + (uint32_t)nq * 16 * ROWB + koff);
            #pragma unroll
            for (int mi = 0; mi < 4; mi++)
                #pragma unroll
                for (int ni = 0; ni < 4; ni++)
                    mma_fp16(acc[mi][ni], a[mi], &bb[ni >> 1][(ni & 1) * 2]);
        }
        __syncthreads();
    }
    __syncthreads();

    __half* vt = reinterpret_cast<__half*>(smem);
    #pragma unroll
    for (int ni = 0; ni < 4; ni++) {
        int col = wn * 32 + ni * 8 + (lane & 3) * 2;
        #pragma unroll
        for (int mi = 0; mi < 4; mi++) {
            int r0 = wm * 64 + mi * 16 + (lane >> 2);
            #pragma unroll
            for (int half = 0; half < 2; half++) {
                int row = r0 + half * 8;
                vt[row * VP + col]     = __float2half(acc[mi][ni][half * 2 + 0]);
                vt[row * VP + col + 1] = __float2half(acc[mi][ni][half * 2 + 1]);
            }
        }
    }
    __syncthreads();

    const int poff = z * (11 - z) / 2;
    for (int j = z + 1; j < Fn; j++) {
        int p = poff + j - z - 1;
        for (int idx = tid; idx < 128 * 64; idx += 256) {
            int row = idx >> 6, c2 = idx & 63;
            size_t gb = (size_t)(bm + row);
            __half2 vv = *reinterpret_cast<__half2*>(&vt[row * VP + c2 * 2]);
            __half2 sv = *reinterpret_cast<const __half2*>(&g_s[gb * (Fn * Dn) + j * Dn + c2 * 2]);
            float v0 = __half2float(__low2half(vv))  * __half2float(__low2half(sv));
            float v1 = __half2float(__high2half(vv)) * __half2float(__high2half(sv));
            *reinterpret_cast<__half2*>(&g_c[gb * CINn + Fn * Dn + p * Dn + c2 * 2]) =
                __halves2half2(__float2half(v0), __float2half(v1));
        }
    }
}

// ---------------- k_mma256: BN=256, warp tile 64x64 (MLP layers) -------------
#define BM2 128
#define BN2 256
#define OFF_A2  0u
#define OFF_B2  10240u
#define STAGEB2 30720u
#define NSTAGE2 4
#define SMEM_MMA2 (NSTAGE2 * STAGEB2)

__global__ __launch_bounds__(256, 1) void k_mma256(
    const __half* __restrict__ A, const __half* __restrict__ B,
    int K,
    float* __restrict__ outf, __half* __restrict__ oh, int ldc,
    const float* __restrict__ bias, const float* __restrict__ bng,
    const float* __restrict__ bnb, int mode)
{
    extern __shared__ char smem[];
    const uint32_t sbase = smem_u32(smem);
    const int tid = threadIdx.x;
    const int lane = tid & 31, wid = tid >> 5;
    const int wm = wid >> 2, wn = wid & 3;
    const int bm = blockIdx.y * BM2, bn = blockIdx.x * BN2;

    float acc[4][8][4];
    #pragma unroll
    for (int mi = 0; mi < 4; mi++)
        #pragma unroll
        for (int ni = 0; ni < 8; ni++)
            #pragma unroll
            for (int q = 0; q < 4; q++) acc[mi][ni][q] = 0.f;

    const uint32_t a_base = (uint32_t)(wm * 64 + (lane & 15)) * ROWB + (uint32_t)((lane >> 4) * 16);
    const uint32_t b_base = (uint32_t)(wn * 64 + (lane & 7) + ((lane >> 4) << 3)) * ROWB
                          + (uint32_t)(((lane >> 3) & 1) * 16);

    const int nIter = K / BK;

    auto load_stage = [&](int buf, int k0) {
        uint32_t base = sbase + (uint32_t)buf * STAGEB2;
        #pragma unroll
        for (int half = 0; half < 2; half++) {
            int e = tid + half * 256;
            int r = e >> 2, c = e & 3;
            uint32_t off = (uint32_t)r * ROWB + (uint32_t)c * 16;
            cp16(base + OFF_A2 + off, A + (size_t)(bm + r) * K + k0 + c * 8);
        }
        #pragma unroll
        for (int half = 0; half < 4; half++) {
            int e = tid + half * 256;
            int r = e >> 2, c = e & 3;
            uint32_t off = (uint32_t)r * ROWB + (uint32_t)c * 16;
            cp16(base + OFF_B2 + off, B + (size_t)(bn + r) * K + k0 + c * 8);
        }
    };

    load_stage(0, 0);
    cp_commit();
    load_stage(1, BK);
    cp_commit();
    load_stage(2, 2 * BK);
    cp_commit();

    for (int it = 0; it < nIter; it++) {
        if (it + 3 < nIter) {
            load_stage((it + 3) & 3, (it + 3) * BK);
            cp_commit();
            cp_wait<3>();
        } else if (it + 2 < nIter) {
            cp_wait<2>();
        } else if (it + 1 < nIter) {
            cp_wait<1>();
        } else {
            cp_wait<0>();
        }
        __syncthreads();

        uint32_t base = sbase + (uint32_t)(it & 3) * STAGEB2;
        #pragma unroll
        for (int ks = 0; ks < 2; ks++) {
            uint32_t koff = (uint32_t)ks * 32;
            uint32_t a[4][4], bb[4][4];
            #pragma unroll
            for (int mi = 0; mi < 4; mi++)
                ldsm4(a[mi], base + OFF_A2 + a_base + (uint32_t)mi * 16 * ROWB + koff);
            #pragma unroll
            for (int nq = 0; nq < 4; nq++)
                ldsm4(bb[nq], base + OFF_B2 + b_base + (uint32_t)nq * 16 * ROWB + koff);
            #pragma unroll
            for (int mi = 0; mi < 4; mi++)
                #pragma unroll
                for (int ni = 0; ni < 8; ni++)
                    mma_fp16(acc[mi][ni], a[mi], &bb[ni >> 1][(ni & 1) * 2]);
        }
        __syncthreads();
    }

    const float bnscale = 0.999995000037499688f;  // 1/sqrt(1+1e-5)
    #pragma unroll
    for (int ni = 0; ni < 8; ni++) {
        int col = bn + wn * 64 + ni * 8 + (lane & 3) * 2;
        float bi0 = bias[col],         bi1 = bias[col + 1];
        float g0 = bng[col] * bnscale, g1 = bng[col + 1] * bnscale;
        float bb0 = bnb[col],          bb1 = bnb[col + 1];
        #pragma unroll
        for (int mi = 0; mi < 4; mi++) {
            int r0 = bm + wm * 64 + mi * 16 + (lane >> 2);
            #pragma unroll
            for (int half = 0; half < 2; half++) {
                int row = r0 + half * 8;
                float v0 = acc[mi][ni][half * 2 + 0];
                float v1 = acc[mi][ni][half * 2 + 1];
                v0 = (v0 + bi0) * g0 + bb0;
                v1 = (v1 + bi1) * g1 + bb1;
                v0 = 0.5f * v0 * (1.f + erff(v0 * 0.70710678118654752f));
                v1 = 0.5f * v1 * (1.f + erff(v1 * 0.70710678118654752f));
                if (mode == 2) {
                    outf[(size_t)row * ldc + col]     = v0;
                    outf[(size_t)row * ldc + col + 1] = v1;
                } else {
                    oh[(size_t)row * ldc + col]     = __float2half(v0);
                    oh[(size_t)row * ldc + col + 1] = __float2half(v1);
                }
            }
        }
    }
}

// ---------------- K5: final dot + sigmoid ------------------------------------
__global__ __launch_bounds__(256) void k_final(
    const float* __restrict__ w3, const float* __restrict__ b3,
    float* __restrict__ out)
{
    int warp = threadIdx.x >> 5, lane = threadIdx.x & 31;
    int b = blockIdx.x * 8 + warp;
    const float* hh = g_h2 + (size_t)b * H2N;
    float acc = 0.f;
    #pragma unroll
    for (int i = 0; i < 8; i++) acc = fmaf(hh[lane + i * 32], w3[lane + i * 32], acc);
    #pragma unroll
    for (int o = 16; o; o >>= 1) acc += __shfl_xor_sync(0xffffffffu, acc, o);
    if (!lane) out[b] = 1.f / (1.f + expf(-(acc + b3[0])));
}

// ---------------- launch -----------------------------------------------------
extern "C" void kernel_launch(void* const* d_in, const int* in_sizes, int n_in,
                              void* d_out, int out_size)
{
    const int*   item_id  = (const int*)  d_in[0];
    const float* item_mm  = (const float*)d_in[1];
    const int*   likes    = (const int*)  d_in[2];
    const int*   views    = (const int*)  d_in[3];
    const int*   item_seq = (const int*)  d_in[4];
    const float* item_emb = (const float*)d_in[5];
    const float* cate_emb = (const float*)d_in[6];
    const float* mm_w     = (const float*)d_in[7];
    const float* mm_b     = (const float*)d_in[8];
    const float* ln_g     = (const float*)d_in[9];
    const float* ln_b     = (const float*)d_in[10];
    const float* gnn_W    = (const float*)d_in[11];
    const float* gnn_a    = (const float*)d_in[12];
    const float* se_w1    = (const float*)d_in[13];
    const float* se_b1    = (const float*)d_in[14];
    const float* se_w2    = (const float*)d_in[15];
    const float* se_b2    = (const float*)d_in[16];
    const float* bi_W     = (const float*)d_in[17];
    const float* w1       = (const float*)d_in[18];
    const float* b1       = (const float*)d_in[19];
    const float* bn1g     = (const float*)d_in[20];
    const float* bn1b     = (const float*)d_in[21];
    const float* w2       = (const float*)d_in[22];
    const float* b2       = (const float*)d_in[23];
    const float* bn2g     = (const float*)d_in[24];
    const float* bn2b     = (const float*)d_in[25];
    const float* w3       = (const float*)d_in[26];
    const float* b3       = (const float*)d_in[27];
    float* out = (float*)d_out;

    float *ph2;
    __half *ps, *pc, *ph1, *pw1, *pw2, *pwb;
    cudaGetSymbolAddress((void**)&ps,   g_s);
    cudaGetSymbolAddress((void**)&ph2,  g_h2);
    cudaGetSymbolAddress((void**)&pc,   g_c);
    cudaGetSymbolAddress((void**)&ph1,  g_h1);
    cudaGetSymbolAddress((void**)&pw1,  g_w1t);
    cudaGetSymbolAddress((void**)&pw2,  g_w2t);
    cudaGetSymbolAddress((void**)&pwb,  g_wb);

    cudaFuncSetAttribute(k_feat_gnn, cudaFuncAttributeMaxDynamicSharedMemorySize, FG_SMEM);
    cudaFuncSetAttribute(k_mma128, cudaFuncAttributeMaxDynamicSharedMemorySize, SMEM_MMA);
    cudaFuncSetAttribute(k_mma256, cudaFuncAttributeMaxDynamicSharedMemorySize, SMEM_MMA2);

    // weight prep
    {
        dim3 g1(CINn / 32, H1N / 32);
        k_wt<<<g1, 256>>>(w1, pw1, CINn, H1N);
        dim3 g2(H1N / 32, H2N / 32);
        k_wt<<<g2, 256>>>(w2, pw2, H1N, H2N);
        dim3 g3(Dn / 32, Dn / 32, 5);
        k_wbi<<<g3, 256>>>(bi_W);
        k_wg<<<(4 * 128 * 32 + 255) / 256, 256>>>(gnn_W);
    }

    // fused features + GNN(HMMA) + SE
    k_feat_gnn<<<Bn, 128, FG_SMEM>>>(item_id, item_mm, likes, views, item_seq,
                                     item_emb, cate_emb, mm_w, mm_b, ln_g, ln_b,
                                     gnn_a, se_w1, se_b1, se_w2, se_b2);

    // bilinear + fused pairs: z = field i; writes c[:, 768:] directly
    {
        dim3 grid(1, Bn / BM, 5);
        k_mma128<<<grid, 256, SMEM_MMA>>>(ps, pwb, Dn, Fn * Dn, Dn, (long)Dn * Dn);
    }

    // layer 1: c @ w1 (+bias,bn,gelu) -> h1 (fp16)
    {
        dim3 grid(H1N / BN2, Bn / BM2, 1);
        k_mma256<<<grid, 256, SMEM_MMA2>>>(pc, pw1, CINn,
                                           nullptr, ph1, H1N, b1, bn1g, bn1b, 1);
    }
    // layer 2: h1 @ w2 (+bias,bn,gelu) -> h2 (fp32)
    {
        dim3 grid(H2N / BN2, Bn / BM2, 1);
        k_mma256<<<grid, 256, SMEM_MMA2>>>(ph1, pw2, H1N,
                                           ph2, nullptr, H2N, b2, bn2g, bn2b, 2);
    }
    k_final<<<Bn / 8, 256>>>(w3, b3, out);
}

// round 17
// speedup vs baseline: 1.1568x; 1.1568x over previous
#include <cuda_runtime.h>
#include <cuda_fp16.h>
#include <math.h>
#include <stdint.h>

#define Bn 16384
#define Ln 50
#define Dn 128
#define Fn 6
#define CINn 2688
#define H1N 512
#define H2N 256

// ---------------- scratch (static device globals) ---------------------------
__device__ __align__(16) __half g_s  [Bn * Fn * Dn];   // fp16 SE-scaled feats
__device__ __align__(16) __half g_c  [Bn * CINn];      // fp16 activations
__device__ __align__(16) __half g_h1 [Bn * H1N];
__device__ __align__(16) float g_h2 [Bn * H2N];
__device__ __align__(16) __half g_w1t[H1N * CINn];     // fp16 weights (transposed)
__device__ __align__(16) __half g_w2t[H2N * H1N];
__device__ __align__(16) __half g_wb [5 * Dn * Dn];    // bi_W as [f][e][d]

// ---------------- PTX helpers (sm_80-level only) -----------------------------
__device__ __forceinline__ uint32_t smem_u32(const void* p) {
    uint32_t a;
    asm("{ .reg .u64 t; cvta.to.shared.u64 t, %1; cvt.u32.u64 %0, t; }" : "=r"(a) : "l"(p));
    return a;
}
__device__ __forceinline__ void cp16(uint32_t dst, const void* src) {
    asm volatile("cp.async.cg.shared.global [%0], [%1], 16;" :: "r"(dst), "l"(src));
}
__device__ __forceinline__ void cp_commit() {
    asm volatile("cp.async.commit_group;" ::: "memory");
}
template <int N>
__device__ __forceinline__ void cp_wait() {
    asm volatile("cp.async.wait_group %0;" :: "n"(N) : "memory");
}
__device__ __forceinline__ void ldsm4(uint32_t* r, uint32_t addr) {
    asm volatile("ldmatrix.sync.aligned.m8n8.x4.shared.b16 {%0,%1,%2,%3}, [%4];"
                 : "=r"(r[0]), "=r"(r[1]), "=r"(r[2]), "=r"(r[3]) : "r"(addr));
}
__device__ __forceinline__ void mma_fp16(float* d, const uint32_t* a, const uint32_t* b) {
    asm volatile(
        "mma.sync.aligned.m16n8k16.row.col.f32.f16.f16.f32 "
        "{%0,%1,%2,%3}, {%4,%5,%6,%7}, {%8,%9}, {%0,%1,%2,%3};"
        : "+f"(d[0]), "+f"(d[1]), "+f"(d[2]), "+f"(d[3])
        : "r"(a[0]), "r"(a[1]), "r"(a[2]), "r"(a[3]), "r"(b[0]), "r"(b[1]));
}

// ---------------- K1: fused features + GAT + SE ------------------------------
// Exploits x[:,0,:] == 0 (user_feat): hp[0] = 0, ei[0] = ej[0] = 0.
__global__ __launch_bounds__(128) void k_feat_gnn(
    const int* __restrict__ item_id, const float* __restrict__ item_mm,
    const int* __restrict__ likes, const int* __restrict__ views,
    const int* __restrict__ item_seq, const float* __restrict__ item_emb,
    const float* __restrict__ cate_emb, const float* __restrict__ mm_w,
    const float* __restrict__ mm_b, const float* __restrict__ ln_g,
    const float* __restrict__ ln_b,
    const float* __restrict__ gnn_W, const float* __restrict__ gnn_a,
    const float* __restrict__ se_w1, const float* __restrict__ se_b1,
    const float* __restrict__ se_w2, const float* __restrict__ se_b2)
{
    int b = blockIdx.x, t = threadIdx.x;
    int lane = t & 31, w = t >> 5;
    int h = w;
    __shared__ float xs[Fn * Dn];
    __shared__ float sm[Dn];
    __shared__ float red[8];
    __shared__ float red2[4 * Fn];
    __shared__ int sseq[Ln];

    sm[t] = item_mm[b * Dn + t];
    if (t < Ln) sseq[t] = item_seq[b * Ln + t];
    __syncthreads();

    float y = mm_b[t];
    {
        const float* Wc = mm_w + t;
        #pragma unroll
        for (int c = 0; c < 4; c++) {
            float wv[32];
            #pragma unroll
            for (int q = 0; q < 32; q++) wv[q] = Wc[(c * 32 + q) * Dn];
            const float4* xv = reinterpret_cast<const float4*>(&sm[c * 32]);
            #pragma unroll
            for (int q8 = 0; q8 < 8; q8++) {
                float4 v = xv[q8];
                y = fmaf(v.x, wv[q8 * 4 + 0], y);
                y = fmaf(v.y, wv[q8 * 4 + 1], y);
                y = fmaf(v.z, wv[q8 * 4 + 2], y);
                y = fmaf(v.w, wv[q8 * 4 + 3], y);
            }
        }
    }

    float s1 = y, s2 = y * y;
    #pragma unroll
    for (int o = 16; o; o >>= 1) {
        s1 += __shfl_xor_sync(0xffffffffu, s1, o);
        s2 += __shfl_xor_sync(0xffffffffu, s2, o);
    }
    if (!lane) { red[w] = s1; red[4 + w] = s2; }
    __syncthreads();
    float mu = (red[0] + red[1] + red[2] + red[3]) * (1.f / Dn);
    float m2 = (red[4] + red[5] + red[6] + red[7]) * (1.f / Dn);
    float var = m2 - mu * mu;
    float yn = (y - mu) * rsqrtf(var + 1e-5f) * ln_g[t] + ln_b[t];
    float img = 0.5f * yn * (1.f + erff(yn * 0.70710678118654752f));

    // branch-free masked mean: item_emb[0] == 0 by construction
    float hs = 0.f;
    int cnt = 0;
    #pragma unroll 10
    for (int l = 0; l < Ln; l++) {
        int id = sseq[l];
        hs += item_emb[(size_t)id * Dn + t];
        cnt += (id != 0);
    }
    float hist = hs / fmaxf((float)cnt, 1.f);

    xs[0 * Dn + t] = 0.f;
    xs[1 * Dn + t] = cate_emb[likes[b] * Dn + t];
    xs[2 * Dn + t] = cate_emb[views[b] * Dn + t];
    xs[3 * Dn + t] = item_emb[(size_t)item_id[b] * Dn + t];
    xs[4 * Dn + t] = img;
    xs[5 * Dn + t] = hist;
    __syncthreads();

    // hp[n] = sum_i xs[n][i] * W[h][i][lane]; n = 0 is identically zero.
    float hp[Fn];
    #pragma unroll
    for (int n = 0; n < Fn; n++) hp[n] = 0.f;
    const float* Wh = gnn_W + h * (Dn * 32) + lane;
    #pragma unroll
    for (int c = 0; c < 4; c++) {
        float wv[32];
        #pragma unroll
        for (int q = 0; q < 32; q++) wv[q] = Wh[(c * 32 + q) * 32];
        #pragma unroll
        for (int n = 1; n < Fn; n++) {
            const float4* xv = reinterpret_cast<const float4*>(&xs[n * Dn + c * 32]);
            float a = hp[n];
            #pragma unroll
            for (int q8 = 0; q8 < 8; q8++) {
                float4 v = xv[q8];
                a = fmaf(v.x, wv[q8 * 4 + 0], a);
                a = fmaf(v.y, wv[q8 * 4 + 1], a);
                a = fmaf(v.z, wv[q8 * 4 + 2], a);
                a = fmaf(v.w, wv[q8 * 4 + 3], a);
            }
            hp[n] = a;
        }
    }

    float a1 = gnn_a[h * 64 + lane];
    float a2 = gnn_a[h * 64 + 32 + lane];
    float ei[Fn], ej[Fn];
    ei[0] = 0.f; ej[0] = 0.f;                 // hp[0] == 0 exactly
    #pragma unroll
    for (int n = 1; n < Fn; n++) {
        float v1 = hp[n] * a1, v2 = hp[n] * a2;
        #pragma unroll
        for (int o = 16; o; o >>= 1) {
            v1 += __shfl_xor_sync(0xffffffffu, v1, o);
            v2 += __shfl_xor_sync(0xffffffffu, v2, o);
        }
        ei[n] = v1; ej[n] = v2;
    }

    float gnn[Fn];
    #pragma unroll
    for (int n = 0; n < Fn; n++) {
        float em[Fn], mx = -1e30f;
        #pragma unroll
        for (int m = 0; m < Fn; m++) {
            float e = ei[n] + ej[m];
            e = e > 0.f ? e : 0.2f * e;
            em[m] = e; mx = fmaxf(mx, e);
        }
        float ss = 0.f;
        #pragma unroll
        for (int m = 0; m < Fn; m++) { em[m] = expf(em[m] - mx); ss += em[m]; }
        float inv = 1.f / ss, acc = 0.f;
        #pragma unroll
        for (int m = 1; m < Fn; m++) acc = fmaf(em[m], hp[m], acc);  // hp[0]=0
        float hn = acc * inv + xs[n * Dn + t];
        gnn[n] = hn > 0.f ? hn : expm1f(hn);
    }

    #pragma unroll
    for (int n = 0; n < Fn; n++) {
        float v = gnn[n];
        #pragma unroll
        for (int o = 16; o; o >>= 1) v += __shfl_xor_sync(0xffffffffu, v, o);
        if (!lane) red2[h * Fn + n] = v;
    }
    __syncthreads();

    float wv[Fn];
    {
        float z[Fn];
        #pragma unroll
        for (int n = 0; n < Fn; n++)
            z[n] = (red2[0 * Fn + n] + red2[1 * Fn + n] + red2[2 * Fn + n] + red2[3 * Fn + n]) * (1.f / Dn);
        float a[3];
        #pragma unroll
        for (int k = 0; k < 3; k++) {
            float v = se_b1[k];
            #pragma unroll
            for (int n = 0; n < Fn; n++) v = fmaf(z[n], se_w1[n * 3 + k], v);
            a[k] = fmaxf(v, 0.f);
        }
        #pragma unroll
        for (int f = 0; f < Fn; f++) {
            float v = se_b2[f];
            #pragma unroll
            for (int k = 0; k < 3; k++) v = fmaf(a[k], se_w2[k * 6 + f], v);
            wv[f] = 1.f / (1.f + expf(-v));
        }
    }

    __half* ch = g_c + (size_t)b * CINn;
    __half* sb = g_s + (size_t)b * Fn * Dn;
    #pragma unroll
    for (int n = 0; n < Fn; n++) {
        float v = gnn[n];
        ch[n * Dn + t] = __float2half(v);
        sb[n * Dn + t] = __float2half(v * wv[n]);
    }
}

// ---------------- weight prep: tiled transpose + fp16 ------------------------
__global__ __launch_bounds__(256) void k_wt(
    const float* __restrict__ W, __half* __restrict__ T, int K, int N)
{
    __shared__ float tile[32][33];
    int kb = blockIdx.x * 32, nb = blockIdx.y * 32;
    int tx = threadIdx.x & 31, ty = threadIdx.x >> 5;
    #pragma unroll
    for (int i = 0; i < 32; i += 8)
        tile[ty + i][tx] = W[(size_t)(kb + ty + i) * N + nb + tx];
    __syncthreads();
    #pragma unroll
    for (int i = 0; i < 32; i += 8)
        T[(size_t)(nb + ty + i) * K + kb + tx] = __float2half(tile[tx][ty + i]);
}
__global__ __launch_bounds__(256) void k_wbi(const float* __restrict__ W)
{
    __shared__ float tile[32][33];
    int f = blockIdx.z;
    int db = blockIdx.x * 32, eb = blockIdx.y * 32;
    int tx = threadIdx.x & 31, ty = threadIdx.x >> 5;
    const float* Wf = W + (size_t)f * Dn * Dn;
    __half* Tf = g_wb + (size_t)f * Dn * Dn;
    #pragma unroll
    for (int i = 0; i < 32; i += 8)
        tile[ty + i][tx] = Wf[(db + ty + i) * Dn + eb + tx];
    __syncthreads();
    #pragma unroll
    for (int i = 0; i < 32; i += 8)
        Tf[(eb + ty + i) * Dn + db + tx] = __float2half(tile[tx][ty + i]);
}

// ---------------- shared GEMM constants --------------------------------------
#define BK 32
#define ROWB 80u

// ---------------- k_mma128: bilinear + fused pairs (coalesced epilogue) ------
#define BM 128
#define BN 128
#define OFF_A  0u
#define OFF_B  10240u
#define STAGEB 20480u
#define NSTAGE 4
#define SMEM_MMA (NSTAGE * STAGEB)
#define VP 132

__global__ __launch_bounds__(256, 1) void k_mma128(
    const __half* __restrict__ A, const __half* __restrict__ B,
    int K, int lda, long az, long bz)
{
    extern __shared__ char smem[];
    const uint32_t sbase = smem_u32(smem);
    const int tid = threadIdx.x;
    const int lane = tid & 31, wid = tid >> 5;
    const int wm = wid >> 2, wn = wid & 3;
    const int bm = blockIdx.y * BM, bn = blockIdx.x * BN;
    const int z = blockIdx.z;
    A += (size_t)z * az;
    B += (size_t)z * bz;

    float acc[4][4][4];
    #pragma unroll
    for (int mi = 0; mi < 4; mi++)
        #pragma unroll
        for (int ni = 0; ni < 4; ni++)
            #pragma unroll
            for (int q = 0; q < 4; q++) acc[mi][ni][q] = 0.f;

    const uint32_t a_base = (uint32_t)(wm * 64 + (lane & 15)) * ROWB + (uint32_t)((lane >> 4) * 16);
    const uint32_t b_base = (uint32_t)(wn * 32 + (lane & 7) + ((lane >> 4) << 3)) * ROWB
                          + (uint32_t)(((lane >> 3) & 1) * 16);

    const int nIter = K / BK;

    auto load_stage = [&](int buf, int k0) {
        uint32_t base = sbase + (uint32_t)buf * STAGEB;
        #pragma unroll
        for (int half = 0; half < 2; half++) {
            int e = tid + half * 256;
            int r = e >> 2, c = e & 3;
            uint32_t off = (uint32_t)r * ROWB + (uint32_t)c * 16;
            cp16(base + OFF_A + off, A + (size_t)(bm + r) * lda + k0 + c * 8);
            cp16(base + OFF_B + off, B + (size_t)(bn + r) * K   + k0 + c * 8);
        }
    };

    load_stage(0, 0);
    cp_commit();
    load_stage(1, BK);
    cp_commit();
    load_stage(2, 2 * BK);
    cp_commit();

    for (int it = 0; it < nIter; it++) {
        if (it + 3 < nIter) {
            load_stage((it + 3) & 3, (it + 3) * BK);
            cp_commit();
            cp_wait<3>();
        } else if (it + 2 < nIter) {
            cp_wait<2>();
        } else if (it + 1 < nIter) {
            cp_wait<1>();
        } else {
            cp_wait<0>();
        }
        __syncthreads();

        uint32_t base = sbase + (uint32_t)(it & 3) * STAGEB;
        #pragma unroll
        for (int ks = 0; ks < 2; ks++) {
            uint32_t koff = (uint32_t)ks * 32;
            uint32_t a[4][4], bb[2][4];
            #pragma unroll
            for (int mi = 0; mi < 4; mi++)
                ldsm4(a[mi], base + OFF_A + a_base + (uint32_t)mi * 16 * ROWB + koff);
            #pragma unroll
            for (int nq = 0; nq < 2; nq++)
                ldsm4(bb[nq], base + OFF_B + b_base + (uint32_t)nq * 16 * ROWB + koff);
            #pragma unroll
            for (int mi = 0; mi < 4; mi++)
                #pragma unroll
                for (int ni = 0; ni < 4; ni++)
                    mma_fp16(acc[mi][ni], a[mi], &bb[ni >> 1][(ni & 1) * 2]);
        }
        __syncthreads();
    }
    __syncthreads();

    __half* vt = reinterpret_cast<__half*>(smem);
    #pragma unroll
    for (int ni = 0; ni < 4; ni++) {
        int col = wn * 32 + ni * 8 + (lane & 3) * 2;
        #pragma unroll
        for (int mi = 0; mi < 4; mi++) {
            int r0 = wm * 64 + mi * 16 + (lane >> 2);
            #pragma unroll
            for (int half = 0; half < 2; half++) {
                int row = r0 + half * 8;
                vt[row * VP + col]     = __float2half(acc[mi][ni][half * 2 + 0]);
                vt[row * VP + col + 1] = __float2half(acc[mi][ni][half * 2 + 1]);
            }
        }
    }
    __syncthreads();

    const int poff = z * (11 - z) / 2;
    for (int j = z + 1; j < Fn; j++) {
        int p = poff + j - z - 1;
        for (int idx = tid; idx < 128 * 64; idx += 256) {
            int row = idx >> 6, c2 = idx & 63;
            size_t gb = (size_t)(bm + row);
            __half2 vv = *reinterpret_cast<__half2*>(&vt[row * VP + c2 * 2]);
            __half2 sv = *reinterpret_cast<const __half2*>(&g_s[gb * (Fn * Dn) + j * Dn + c2 * 2]);
            float v0 = __half2float(__low2half(vv))  * __half2float(__low2half(sv));
            float v1 = __half2float(__high2half(vv)) * __half2float(__high2half(sv));
            *reinterpret_cast<__half2*>(&g_c[gb * CINn + Fn * Dn + p * Dn + c2 * 2]) =
                __halves2half2(__float2half(v0), __float2half(v1));
        }
    }
}

// ---------------- k_mma256: BN=256, warp tile 64x64 (MLP layers) -------------
#define BM2 128
#define BN2 256
#define OFF_A2  0u
#define OFF_B2  10240u
#define STAGEB2 30720u
#define NSTAGE2 4
#define SMEM_MMA2 (NSTAGE2 * STAGEB2)

__global__ __launch_bounds__(256, 1) void k_mma256(
    const __half* __restrict__ A, const __half* __restrict__ B,
    int K,
    float* __restrict__ outf, __half* __restrict__ oh, int ldc,
    const float* __restrict__ bias, const float* __restrict__ bng,
    const float* __restrict__ bnb, int mode)
{
    extern __shared__ char smem[];
    const uint32_t sbase = smem_u32(smem);
    const int tid = threadIdx.x;
    const int lane = tid & 31, wid = tid >> 5;
    const int wm = wid >> 2, wn = wid & 3;
    const int bm = blockIdx.y * BM2, bn = blockIdx.x * BN2;

    float acc[4][8][4];
    #pragma unroll
    for (int mi = 0; mi < 4; mi++)
        #pragma unroll
        for (int ni = 0; ni < 8; ni++)
            #pragma unroll
            for (int q = 0; q < 4; q++) acc[mi][ni][q] = 0.f;

    const uint32_t a_base = (uint32_t)(wm * 64 + (lane & 15)) * ROWB + (uint32_t)((lane >> 4) * 16);
    const uint32_t b_base = (uint32_t)(wn * 64 + (lane & 7) + ((lane >> 4) << 3)) * ROWB
                          + (uint32_t)(((lane >> 3) & 1) * 16);

    const int nIter = K / BK;

    auto load_stage = [&](int buf, int k0) {
        uint32_t base = sbase + (uint32_t)buf * STAGEB2;
        #pragma unroll
        for (int half = 0; half < 2; half++) {
            int e = tid + half * 256;
            int r = e >> 2, c = e & 3;
            uint32_t off = (uint32_t)r * ROWB + (uint32_t)c * 16;
            cp16(base + OFF_A2 + off, A + (size_t)(bm + r) * K + k0 + c * 8);
        }
        #pragma unroll
        for (int half = 0; half < 4; half++) {
            int e = tid + half * 256;
            int r = e >> 2, c = e & 3;
            uint32_t off = (uint32_t)r * ROWB + (uint32_t)c * 16;
            cp16(base + OFF_B2 + off, B + (size_t)(bn + r) * K + k0 + c * 8);
        }
    };

    load_stage(0, 0);
    cp_commit();
    load_stage(1, BK);
    cp_commit();
    load_stage(2, 2 * BK);
    cp_commit();

    for (int it = 0; it < nIter; it++) {
        if (it + 3 < nIter) {
            load_stage((it + 3) & 3, (it + 3) * BK);
            cp_commit();
            cp_wait<3>();
        } else if (it + 2 < nIter) {
            cp_wait<2>();
        } else if (it + 1 < nIter) {
            cp_wait<1>();
        } else {
            cp_wait<0>();
        }
        __syncthreads();

        uint32_t base = sbase + (uint32_t)(it & 3) * STAGEB2;
        #pragma unroll
        for (int ks = 0; ks < 2; ks++) {
            uint32_t koff = (uint32_t)ks * 32;
            uint32_t a[4][4], bb[4][4];
            #pragma unroll
            for (int mi = 0; mi < 4; mi++)
                ldsm4(a[mi], base + OFF_A2 + a_base + (uint32_t)mi * 16 * ROWB + koff);
            #pragma unroll
            for (int nq = 0; nq < 4; nq++)
                ldsm4(bb[nq], base + OFF_B2 + b_base + (uint32_t)nq * 16 * ROWB + koff);
            #pragma unroll
            for (int mi = 0; mi < 4; mi++)
                #pragma unroll
                for (int ni = 0; ni < 8; ni++)
                    mma_fp16(acc[mi][ni], a[mi], &bb[ni >> 1][(ni & 1) * 2]);
        }
        __syncthreads();
    }

    const float bnscale = 0.999995000037499688f;  // 1/sqrt(1+1e-5)
    #pragma unroll
    for (int ni = 0; ni < 8; ni++) {
        int col = bn + wn * 64 + ni * 8 + (lane & 3) * 2;
        float bi0 = bias[col],         bi1 = bias[col + 1];
        float g0 = bng[col] * bnscale, g1 = bng[col + 1] * bnscale;
        float bb0 = bnb[col],          bb1 = bnb[col + 1];
        #pragma unroll
        for (int mi = 0; mi < 4; mi++) {
            int r0 = bm + wm * 64 + mi * 16 + (lane >> 2);
            #pragma unroll
            for (int half = 0; half < 2; half++) {
                int row = r0 + half * 8;
                float v0 = acc[mi][ni][half * 2 + 0];
                float v1 = acc[mi][ni][half * 2 + 1];
                v0 = (v0 + bi0) * g0 + bb0;
                v1 = (v1 + bi1) * g1 + bb1;
                v0 = 0.5f * v0 * (1.f + erff(v0 * 0.70710678118654752f));
                v1 = 0.5f * v1 * (1.f + erff(v1 * 0.70710678118654752f));
                if (mode == 2) {
                    outf[(size_t)row * ldc + col]     = v0;
                    outf[(size_t)row * ldc + col + 1] = v1;
                } else {
                    oh[(size_t)row * ldc + col]     = __float2half(v0);
                    oh[(size_t)row * ldc + col + 1] = __float2half(v1);
                }
            }
        }
    }
}

// ---------------- K5: final dot + sigmoid ------------------------------------
__global__ __launch_bounds__(256) void k_final(
    const float* __restrict__ w3, const float* __restrict__ b3,
    float* __restrict__ out)
{
    int warp = threadIdx.x >> 5, lane = threadIdx.x & 31;
    int b = blockIdx.x * 8 + warp;
    const float* hh = g_h2 + (size_t)b * H2N;
    float acc = 0.f;
    #pragma unroll
    for (int i = 0; i < 8; i++) acc = fmaf(hh[lane + i * 32], w3[lane + i * 32], acc);
    #pragma unroll
    for (int o = 16; o; o >>= 1) acc += __shfl_xor_sync(0xffffffffu, acc, o);
    if (!lane) out[b] = 1.f / (1.f + expf(-(acc + b3[0])));
}

// ---------------- launch -----------------------------------------------------
extern "C" void kernel_launch(void* const* d_in, const int* in_sizes, int n_in,
                              void* d_out, int out_size)
{
    const int*   item_id  = (const int*)  d_in[0];
    const float* item_mm  = (const float*)d_in[1];
    const int*   likes    = (const int*)  d_in[2];
    const int*   views    = (const int*)  d_in[3];
    const int*   item_seq = (const int*)  d_in[4];
    const float* item_emb = (const float*)d_in[5];
    const float* cate_emb = (const float*)d_in[6];
    const float* mm_w     = (const float*)d_in[7];
    const float* mm_b     = (const float*)d_in[8];
    const float* ln_g     = (const float*)d_in[9];
    const float* ln_b     = (const float*)d_in[10];
    const float* gnn_W    = (const float*)d_in[11];
    const float* gnn_a    = (const float*)d_in[12];
    const float* se_w1    = (const float*)d_in[13];
    const float* se_b1    = (const float*)d_in[14];
    const float* se_w2    = (const float*)d_in[15];
    const float* se_b2    = (const float*)d_in[16];
    const float* bi_W     = (const float*)d_in[17];
    const float* w1       = (const float*)d_in[18];
    const float* b1       = (const float*)d_in[19];
    const float* bn1g     = (const float*)d_in[20];
    const float* bn1b     = (const float*)d_in[21];
    const float* w2       = (const float*)d_in[22];
    const float* b2       = (const float*)d_in[23];
    const float* bn2g     = (const float*)d_in[24];
    const float* bn2b     = (const float*)d_in[25];
    const float* w3       = (const float*)d_in[26];
    const float* b3       = (const float*)d_in[27];
    float* out = (float*)d_out;

    float *ph2;
    __half *ps, *pc, *ph1, *pw1, *pw2, *pwb;
    cudaGetSymbolAddress((void**)&ps,   g_s);
    cudaGetSymbolAddress((void**)&ph2,  g_h2);
    cudaGetSymbolAddress((void**)&pc,   g_c);
    cudaGetSymbolAddress((void**)&ph1,  g_h1);
    cudaGetSymbolAddress((void**)&pw1,  g_w1t);
    cudaGetSymbolAddress((void**)&pw2,  g_w2t);
    cudaGetSymbolAddress((void**)&pwb,  g_wb);

    cudaFuncSetAttribute(k_mma128, cudaFuncAttributeMaxDynamicSharedMemorySize, SMEM_MMA);
    cudaFuncSetAttribute(k_mma256, cudaFuncAttributeMaxDynamicSharedMemorySize, SMEM_MMA2);

    // weight prep (tiled transpose + fp16)
    {
        dim3 g1(CINn / 32, H1N / 32);
        k_wt<<<g1, 256>>>(w1, pw1, CINn, H1N);
        dim3 g2(H1N / 32, H2N / 32);
        k_wt<<<g2, 256>>>(w2, pw2, H1N, H2N);
        dim3 g3(Dn / 32, Dn / 32, 5);
        k_wbi<<<g3, 256>>>(bi_W);
    }

    // fused features + GNN + SE
    k_feat_gnn<<<Bn, 128>>>(item_id, item_mm, likes, views, item_seq,
                            item_emb, cate_emb, mm_w, mm_b, ln_g, ln_b,
                            gnn_W, gnn_a, se_w1, se_b1, se_w2, se_b2);

    // bilinear + fused pairs: z = field i; writes c[:, 768:] directly
    {
        dim3 grid(1, Bn / BM, 5);
        k_mma128<<<grid, 256, SMEM_MMA>>>(ps, pwb, Dn, Fn * Dn, Dn, (long)Dn * Dn);
    }

    // layer 1: c @ w1 (+bias,bn,gelu) -> h1 (fp16)
    {
        dim3 grid(H1N / BN2, Bn / BM2, 1);
        k_mma256<<<grid, 256, SMEM_MMA2>>>(pc, pw1, CINn,
                                           nullptr, ph1, H1N, b1, bn1g, bn1b, 1);
    }
    // layer 2: h1 @ w2 (+bias,bn,gelu) -> h2 (fp32)
    {
        dim3 grid(H2N / BN2, Bn / BM2, 1);
        k_mma256<<<grid, 256, SMEM_MMA2>>>(ph1, pw2, H1N,
                                           ph2, nullptr, H2N, b2, bn2g, bn2b, 2);
    }
    k_final<<<Bn / 8, 256>>>(w3, b3, out);
}